// round 14
// baseline (speedup 1.0000x reference)
#include <cuda_runtime.h>
#include <stdint.h>

// Shapes (fixed):
//   updates: (32, 64, 64, 128) fp32  -> 16,777,216 elems
//   mask:    same shape, int32 in [0, 2,097,152)
//   output:  (32, 128, 128, 128) fp32 -> 67,108,864 elems (256 MB)
#define N_IN        16777216
#define FLAT_OUT    2097152      // per-batch output slots (8 MB = 2^23 bytes)
#define NBATCH      32
#define BLKS_PER_B  128          // blocks per batch group (1024 threads each)
#define DELAY       2            // scatter batch = zero batch - DELAY
#define ZCHUNK      65536        // bytes zeroed per block (64 KB)
#define ZBUF_BYTES  16384        // smem zero-source buffer (16 KB)

// Per-batch zero-completion counters (reset every launch by init kernel).
__device__ unsigned int g_ctr[NBATCH];

__global__ void init_ctr_kernel() {
    if (threadIdx.x < NBATCH) g_ctr[threadIdx.x] = 0u;
}

__device__ __forceinline__ unsigned int ld_acquire_gpu(const unsigned int* p) {
    unsigned int v;
    asm volatile("ld.acquire.gpu.global.u32 %0, [%1];" : "=r"(v) : "l"(p) : "memory");
    return v;
}

__device__ __forceinline__ void red_release_gpu_add(unsigned int* p, unsigned int v) {
    asm volatile("red.release.gpu.global.add.u32 [%0], %1;" :: "l"(p), "r"(v) : "memory");
}

__device__ __forceinline__ uint32_t smem_u32(const void* p) {
    uint32_t a;
    asm("{ .reg .u64 t; cvta.to.shared.u64 t, %1; cvt.u32.u64 %0, t; }"
        : "=r"(a) : "l"(p));
    return a;
}

// ---------------------------------------------------------------------------
// Fused zero + scatter pipeline — R8 schedule, with the zero phase offloaded
// from the LSU/L1tex path onto the TMA pipe (cp.async.bulk shared->global).
//
//   Block bid (1024 threads):
//     zb = bid >> 7 : zeroes a 64 KB chunk of batch zb's output (zb < 32)
//                     via 4x16KB UBLKCP from an STS-zeroed smem buffer —
//                     BYPASSES the L1tex wavefront queue the scatter REDs
//                     contend in (zero STGs were ~10% of that budget).
//     sb = zb - 2   : scatters a 4096-element input chunk of batch sb after
//                     all 128 zero-blocks of batch sb have published.
//
//   Critical-path discipline (lesson of R9/R11): t0 issues the bulk copies
//   but does NOT wait before the scatter; wait_group + publish happen AFTER
//   the REDs, so TMA completion latency never blocks block progress.
//   Deadlock-free by induction: groups 0/1 never spin and publish promptly;
//   group g spins only on g-2; blocks dispatch in bid order with backfill.
//   Ordering: STS -> bar -> fence.proxy.async -> bulk issue; bulk wait_group
//   -> red.release -> consumer ld.acquire (standard TMA-store+semaphore).
// ---------------------------------------------------------------------------
__global__ void __launch_bounds__(1024, 2) fused_unpool_kernel(
    const float4* __restrict__ upd,
    const int4*   __restrict__ mask,
    float*        __restrict__ out)
{
    __shared__ alignas(128) float4 zbuf[ZBUF_BYTES / 16];   // 16 KB of zeros

    const int bid = blockIdx.x;
    const int t   = threadIdx.x;                // 0..1023
    const int zb  = bid >> 7;                   // batch to zero
    const int c   = bid & (BLKS_PER_B - 1);     // chunk within group
    const int sb  = zb - DELAY;                 // batch to scatter

    const bool do_zero    = (zb < NBATCH);
    const bool do_scatter = (sb >= 0) && (sb < NBATCH);

    // Prefetch scatter inputs (streaming / evict-first: the one-shot 128 MB
    // input read must not evict the zeroed output window from L2).
    float4 u = make_float4(0.f, 0.f, 0.f, 0.f);
    int4   m = make_int4(0, 0, 0, 0);
    if (do_scatter) {
        const int vi = (sb << 17) + (c << 10) + t;  // vec4 index within batch
        u = __ldcs(&upd[vi]);
        m = __ldcs(&mask[vi]);
    }

    // ---- zero phase: fill smem source, then TMA-bulk-store 64 KB ----
    if (do_zero) {
        zbuf[t] = make_float4(0.f, 0.f, 0.f, 0.f);  // 1024*16B = 16 KB exactly
        __syncthreads();
        if (t == 0) {
            // generic-proxy STS writes must be visible to the async proxy
            asm volatile("fence.proxy.async.shared::cta;" ::: "memory");
            const uint32_t s = smem_u32(zbuf);
            char* gp = reinterpret_cast<char*>(out)
                       + ((size_t)zb << 23)     // zb * 8 MB
                       + ((size_t)c  << 16);    // c  * 64 KB
            #pragma unroll
            for (int k = 0; k < 4; k++) {
                asm volatile(
                    "cp.async.bulk.global.shared::cta.bulk_group [%0], [%1], %2;"
                    :: "l"(gp + (size_t)k * ZBUF_BYTES), "r"(s), "r"(ZBUF_BYTES)
                    : "memory");
            }
            asm volatile("cp.async.bulk.commit_group;" ::: "memory");
            // NOTE: no wait here — completion is reaped after the scatter.
        }
    }

    if (do_scatter) {
        // ---- wait until batch sb is fully zeroed (acquire-poll, t0) ----
        if (t == 0) {
            if (ld_acquire_gpu(&g_ctr[sb]) < BLKS_PER_B) {
                do { __nanosleep(32); }
                while (ld_acquire_gpu(&g_ctr[sb]) < BLKS_PER_B);
            }
        }
        __syncthreads();   // broadcast the acquire to the whole CTA

        // ---- scatter: 4 fire-and-forget REDs into the L2-warm window ----
        float* ob = out + ((size_t)sb << 21);               // FLAT_OUT = 2^21
        atomicAdd(ob + m.x, u.x);
        atomicAdd(ob + m.y, u.y);
        atomicAdd(ob + m.z, u.z);
        atomicAdd(ob + m.w, u.w);
    }

    // ---- publish this block's zero chunk (off the critical path) ----
    if (do_zero && t == 0) {
        asm volatile("cp.async.bulk.wait_group 0;" ::: "memory");
        red_release_gpu_add(&g_ctr[zb], 1u);
    }
}

extern "C" void kernel_launch(void* const* d_in, const int* in_sizes, int n_in,
                              void* d_out, int out_size)
{
    const float4* upd  = (const float4*)d_in[0];
    const int4*   mask = (const int4*)  d_in[1];
    float*        out  = (float*)d_out;

    init_ctr_kernel<<<1, 32>>>();

    // 32 zero-groups * 128 blocks + DELAY*128 scatter-only tail blocks.
    const int grid = (NBATCH + DELAY) * BLKS_PER_B;   // 4352
    fused_unpool_kernel<<<grid, 1024>>>(upd, mask, out);
}

// round 15
// speedup vs baseline: 1.0505x; 1.0505x over previous
#include <cuda_runtime.h>
#include <stdint.h>

// Shapes (fixed):
//   updates: (32, 64, 64, 128) fp32  -> 16,777,216 elems
//   mask:    same shape, int32 in [0, 2,097,152)
//   output:  (32, 128, 128, 128) fp32 -> 67,108,864 elems (256 MB)
#define N_IN        16777216
#define FLAT_OUT    2097152      // per-batch output slots (8 MB)
#define N_OUT       67108864
#define NBATCH      32
#define BLKS_PER_B  128          // blocks per batch group (1024 threads each)
#define DELAY       2            // scatter batch = zero batch - DELAY

// Per-batch zero-completion counters (reset every launch by init kernel).
__device__ unsigned int g_ctr[NBATCH];

__global__ void init_ctr_kernel() {
    if (threadIdx.x < NBATCH) g_ctr[threadIdx.x] = 0u;
}

__device__ __forceinline__ unsigned int ld_acquire_gpu(const unsigned int* p) {
    unsigned int v;
    asm volatile("ld.acquire.gpu.global.u32 %0, [%1];" : "=r"(v) : "l"(p) : "memory");
    return v;
}

__device__ __forceinline__ void red_release_gpu_add(unsigned int* p, unsigned int v) {
    asm volatile("red.release.gpu.global.add.u32 [%0], %1;" :: "l"(p), "r"(v) : "memory");
}

// ---------------------------------------------------------------------------
// Fused zero + scatter pipeline — converged configuration (best: 120.9 us).
//
// Schedule: ONE chunk per block, then die. Block churn + CLC backfill give
// the zero/scatter overlap for free: a block that spins or finishes is
// immediately replaced by a fresh block that starts zeroing. Every attempt
// to restructure this (deeper per-thread work, persistent CTAs, TMA zero
// offload) serialized the acquire/scatter against later forward-progress
// work inside a CTA and regressed.
//
//   Block bid (1024 threads):
//     zb = bid >> 7 : zeroes a 64 KB chunk of batch zb's output (zb < 32)
//     sb = zb - 2   : scatters a 4096-element input chunk of batch sb after
//                     all 128 zero-blocks of batch sb have published.
//   One vec4 per thread -> the scatter is a pure fire-and-forget RED burst;
//   28 regs -> 2 CTAs/SM resident.
//   Producers of batch sb have strictly lower block IDs (>= 256 earlier);
//   producers never spin; CTAs dispatch in bid order with backfill -> no
//   deadlock. BAR.SYNC drains the zero STGs (HW-native on B300); one
//   elected thread publishes with red.release.gpu; consumers poll with
//   ld.acquire.gpu. Scatter REDs then RMW lines still L2-resident
//   (measured: exactly the mandatory ~384 MB of DRAM traffic).
//
// Floor analysis: 113K divergent RED lanes/SM x ~2.07 cyc L1tex wavefront
// replay = ~117 us @NAT; this kernel measures 119.5-120.4 us kernel time.
// ---------------------------------------------------------------------------
__global__ void __launch_bounds__(1024) fused_unpool_kernel(
    const float4* __restrict__ upd,
    const int4*   __restrict__ mask,
    float*        __restrict__ out)
{
    const int bid = blockIdx.x;
    const int t   = threadIdx.x;                // 0..1023
    const int zb  = bid >> 7;                   // batch to zero
    const int c   = bid & (BLKS_PER_B - 1);     // chunk within group
    const int sb  = zb - DELAY;                 // batch to scatter

    const bool do_scatter = (sb >= 0) && (sb < NBATCH);

    // Prefetch scatter inputs (streaming / evict-first: the one-shot 128 MB
    // input read must not evict the zeroed output window from L2). These
    // LDG.128s are in flight during the zero phase below.
    float4 u = make_float4(0.f, 0.f, 0.f, 0.f);
    int4   m = make_int4(0, 0, 0, 0);
    if (do_scatter) {
        const int vi = (sb << 17) + (c << 10) + t;  // vec4 index within batch
        u = __ldcs(&upd[vi]);
        m = __ldcs(&mask[vi]);
    }

    // ---- zero phase: 64 KB = 4096 float4, 4 per thread, coalesced ----
    if (zb < NBATCH) {
        float4* zp = reinterpret_cast<float4*>(out) +
                     ((size_t)zb << 19) + (c << 12) + t;    // FLAT_OUT/4 = 2^19
        const float4 z = make_float4(0.f, 0.f, 0.f, 0.f);
        zp[0]    = z;
        zp[1024] = z;
        zp[2048] = z;
        zp[3072] = z;

        __syncthreads();               // BAR.SYNC drains pending stores (HW)
        if (t == 0) red_release_gpu_add(&g_ctr[zb], 1u);    // publish
    }

    if (!do_scatter) return;

    // ---- wait until batch sb is fully zeroed (acquire-poll, 1 thread) ----
    if (t == 0) {
        if (ld_acquire_gpu(&g_ctr[sb]) < BLKS_PER_B) {
            do { __nanosleep(32); } while (ld_acquire_gpu(&g_ctr[sb]) < BLKS_PER_B);
        }
    }
    __syncthreads();   // broadcast the acquire to the whole CTA

    // ---- scatter phase: 4 fire-and-forget REDs into the L2-warm window ----
    float* ob = out + ((size_t)sb << 21);                   // FLAT_OUT = 2^21
    atomicAdd(ob + m.x, u.x);
    atomicAdd(ob + m.y, u.y);
    atomicAdd(ob + m.z, u.z);
    atomicAdd(ob + m.w, u.w);
}

extern "C" void kernel_launch(void* const* d_in, const int* in_sizes, int n_in,
                              void* d_out, int out_size)
{
    const float4* upd  = (const float4*)d_in[0];
    const int4*   mask = (const int4*)  d_in[1];
    float*        out  = (float*)d_out;

    init_ctr_kernel<<<1, 32>>>();

    // 32 zero-groups * 128 blocks + DELAY*128 scatter-only tail blocks.
    const int grid = (NBATCH + DELAY) * BLKS_PER_B;   // 4352
    fused_unpool_kernel<<<grid, 1024>>>(upd, mask, out);
}